// round 1
// baseline (speedup 1.0000x reference)
#include <cuda_runtime.h>
#include <cstdint>

#define NU 100000
#define NI 50000
#define NN 150000
#define NNZ_E 4800000
#define DIM 64
#define EPS_F 0.1f

// ---------------- static device scratch (allocation-free rule) ----------------
__device__ __align__(256) float g_ego0[(size_t)NN * DIM];   // 38.4 MB
__device__ __align__(256) float g_ego1[(size_t)NN * DIM];   // 38.4 MB
__device__ int  g_rowptr[NN + 1];
__device__ int  g_count[NN];
__device__ int  g_cursor[NN];
__device__ __align__(16) int2 g_edges[NNZ_E];               // 38.4 MB: {col, val-bits}
__device__ int  g_bsum[256];

// ---------------- Threefry-2x32, 20 rounds (exact JAX semantics) ----------------
__host__ __device__ inline void tf2x32(uint32_t k0, uint32_t k1,
                                       uint32_t x0, uint32_t x1,
                                       uint32_t& o0, uint32_t& o1) {
    uint32_t k2 = k0 ^ k1 ^ 0x1BD11BDAu;
    x0 += k0; x1 += k1;
#define TFR(r) { x0 += x1; x1 = (x1 << (r)) | (x1 >> (32 - (r))); x1 ^= x0; }
    TFR(13) TFR(15) TFR(26) TFR(6)   x0 += k1; x1 += k2 + 1u;
    TFR(17) TFR(29) TFR(16) TFR(24)  x0 += k2; x1 += k0 + 2u;
    TFR(13) TFR(15) TFR(26) TFR(6)   x0 += k0; x1 += k1 + 3u;
    TFR(17) TFR(29) TFR(16) TFR(24)  x0 += k1; x1 += k2 + 4u;
    TFR(13) TFR(15) TFR(26) TFR(6)   x0 += k2; x1 += k0 + 5u;
#undef TFR
    o0 = x0; o1 = x1;
}

__device__ __forceinline__ float u01f(uint32_t b) {
    // JAX uniform: bitcast(bits>>9 | 0x3f800000) - 1.0
    return __uint_as_float((b >> 9) | 0x3f800000u) - 1.0f;
}

__device__ __forceinline__ float sgnf(float v) {
    return (v > 0.f) ? 1.f : ((v < 0.f) ? -1.f : 0.f);
}

// ---------------- CSR build ----------------
__global__ void k_zero() {
    int i = blockIdx.x * blockDim.x + threadIdx.x;
    if (i < NN) { g_count[i] = 0; g_cursor[i] = 0; }
}

__global__ void k_hist(const int* __restrict__ rows) {
    int i = blockIdx.x * blockDim.x + threadIdx.x;   // grid exactly covers NNZ_E
    atomicAdd(&g_count[rows[i]], 1);
}

__global__ void k_scan1() {
    __shared__ int sh[1024];
    int gid = blockIdx.x * 1024 + threadIdx.x;
    int v = (gid < NN) ? g_count[gid] : 0;
    sh[threadIdx.x] = v;
    __syncthreads();
#pragma unroll
    for (int off = 1; off < 1024; off <<= 1) {
        int t = (threadIdx.x >= off) ? sh[threadIdx.x - off] : 0;
        __syncthreads();
        sh[threadIdx.x] += t;
        __syncthreads();
    }
    if (gid < NN) g_rowptr[gid] = sh[threadIdx.x] - v;   // exclusive
    if (threadIdx.x == 1023) g_bsum[blockIdx.x] = sh[1023];
}

__global__ void k_scan2(int nb) {
    if (threadIdx.x == 0 && blockIdx.x == 0) {
        int run = 0;
        for (int i = 0; i < nb; i++) { int t = g_bsum[i]; g_bsum[i] = run; run += t; }
        g_rowptr[NN] = run;
    }
}

__global__ void k_scan3() {
    int gid = blockIdx.x * 1024 + threadIdx.x;
    if (gid < NN) g_rowptr[gid] += g_bsum[blockIdx.x];
}

__global__ void k_scatter(const int* __restrict__ rows, const int* __restrict__ cols,
                          const float* __restrict__ vals) {
    int i = blockIdx.x * blockDim.x + threadIdx.x;   // grid exactly covers NNZ_E
    int r = rows[i];
    int p = g_rowptr[r] + atomicAdd(&g_cursor[r], 1);
    g_edges[p] = make_int2(cols[i], __float_as_int(vals[i]));
}

// ---------------- ego0 = concat(user, item) ----------------
__global__ void k_concat(const float4* __restrict__ u, const float4* __restrict__ it) {
    int i = blockIdx.x * blockDim.x + threadIdx.x;   // grid exactly covers NN*DIM/4
    const int NU4 = NU * DIM / 4;
    float4 v = (i < NU4) ? u[i] : it[i - NU4];
    reinterpret_cast<float4*>(g_ego0)[i] = v;
}

// ---------------- fused SpMM-gather + threefry noise + output accumulation ----------
// one warp per row; thread handles dims (2*lane, 2*lane+1)
// mode 0: xout = e; layer_out = e; mean_out = e
// mode 1: xout = e; mean_out += e
// mode 2: mean_out = (mean_out + e) / 3      (xout skipped)
__global__ void k_hop(int src, int mode, uint32_t hk0, uint32_t hk1,
                      float* __restrict__ mean_out, float* __restrict__ layer_out) {
    const float* __restrict__ xin = (src == 0) ? g_ego0 : g_ego1;
    float* __restrict__ xout      = (src == 0) ? g_ego1 : g_ego0;

    int w = (blockIdx.x * blockDim.x + threadIdx.x) >> 5;   // row index
    int lane = threadIdx.x & 31;
    if (w >= NN) return;

    int s = g_rowptr[w];
    int e = g_rowptr[w + 1];
    float acc0 = 0.f, acc1 = 0.f;
#pragma unroll 4
    for (int j = s; j < e; j++) {
        int2 cv = g_edges[j];                                   // uniform across warp
        const float2 xv = *reinterpret_cast<const float2*>(
            xin + (size_t)cv.x * DIM + 2 * lane);
        float v = __int_as_float(cv.y);
        acc0 = fmaf(v, xv.x, acc0);
        acc1 = fmaf(v, xv.y, acc1);
    }

    // noise bits: partitionable threefry, 32-bit => out0 ^ out1 of block (0, idx)
    uint32_t idx = (uint32_t)w * DIM + 2u * (uint32_t)lane;
    uint32_t a0, a1, b0, b1;
    tf2x32(hk0, hk1, 0u, idx,      a0, a1);
    tf2x32(hk0, hk1, 0u, idx + 1u, b0, b1);
    float u0 = u01f(a0 ^ a1);
    float u1 = u01f(b0 ^ b1);

    float ss = fmaf(u0, u0, u1 * u1);
#pragma unroll
    for (int off = 16; off; off >>= 1)
        ss += __shfl_xor_sync(0xffffffffu, ss, off);
    float f = EPS_F / sqrtf(ss);

    float e0 = acc0 + sgnf(acc0) * u0 * f;
    float e1 = acc1 + sgnf(acc1) * u1 * f;

    size_t p = (size_t)w * DIM + 2 * lane;
    float2 ev = make_float2(e0, e1);
    if (mode != 2)
        *reinterpret_cast<float2*>(xout + p) = ev;
    if (mode == 0) {
        *reinterpret_cast<float2*>(layer_out + p) = ev;
        *reinterpret_cast<float2*>(mean_out + p)  = ev;
    } else {
        float2 m = *reinterpret_cast<const float2*>(mean_out + p);
        m.x += e0; m.y += e1;
        if (mode == 2) { m.x *= (1.f / 3.f); m.y *= (1.f / 3.f); }
        *reinterpret_cast<float2*>(mean_out + p) = m;
    }
}

// ---------------- launch ----------------
extern "C" void kernel_launch(void* const* d_in, const int* in_sizes, int n_in,
                              void* d_out, int out_size) {
    const float* user = (const float*)d_in[0];
    const float* item = (const float*)d_in[1];
    const int*   rows = (const int*)d_in[2];
    const int*   cols = (const int*)d_in[3];
    const float* vals = (const float*)d_in[4];
    float* out = (float*)d_out;
    float* mean_out  = out;                       // all_mean (user_all ++ item_all)
    float* layer_out = out + (size_t)NN * DIM;    // layer    (user_layer ++ item_layer)

    // per-hop keys: fold_in(key(42), k) == threefry((0,42),(0,k))
    uint32_t hk0[3], hk1[3];
    for (int k = 0; k < 3; k++)
        tf2x32(0u, 42u, 0u, (uint32_t)k, hk0[k], hk1[k]);

    // CSR build (re-done every launch: deterministic, graph-capturable)
    k_zero<<<(NN + 255) / 256, 256>>>();
    k_hist<<<NNZ_E / 256, 256>>>(rows);
    k_scan1<<<147, 1024>>>();
    k_scan2<<<1, 32>>>(147);
    k_scan3<<<147, 1024>>>();
    k_scatter<<<NNZ_E / 256, 256>>>(rows, cols, vals);

    // ego0 = concat(user, item)
    k_concat<<<(NN * DIM / 4) / 256, 256>>>((const float4*)user, (const float4*)item);

    // 3 fused hops (one warp per row: 150000 warps = 18750 blocks x 256)
    k_hop<<<18750, 256>>>(0, 0, hk0[0], hk1[0], mean_out, layer_out);
    k_hop<<<18750, 256>>>(1, 1, hk0[1], hk1[1], mean_out, layer_out);
    k_hop<<<18750, 256>>>(0, 2, hk0[2], hk1[2], mean_out, layer_out);
}